// round 9
// baseline (speedup 1.0000x reference)
#include <cuda_runtime.h>
#include <cuda_bf16.h>

#define N_NODES 100000
#define N_EDGES 3200000
#define IN_C 5
#define OUT_C 64
#define HID_C 128
#define YSTRIDE 8              // 6 used channels + spare, 32B row = 1 sector

#define SCAN_BS 512
#define SCAN_NB ((N_NODES + SCAN_BS - 1) / SCAN_BS)   // 196

// ---------------------------------------------------------------------------
// Scratch (device globals; no allocation allowed)
// ---------------------------------------------------------------------------
__device__ int   g_deg[N_NODES];
__device__ int   g_bsum[SCAN_NB];
__device__ int   g_rowoff[N_NODES + 1];
__device__ int   g_cursor[N_NODES];
__device__ float g_dinv[N_NODES];
__device__ int   g_adj[N_EDGES];                      // src only, CSR by dst
__device__ float g_ys0[(N_NODES + 1) * YSTRIDE];      // dinv*[x | 1]; row N = 0
__device__ float g_ys1[(N_NODES + 1) * YSTRIDE];      // dinv*out1 (+ ch6 = Â1)
__device__ float g_Wc[IN_C * OUT_C];                  // W1 @ W2  (5x64)
__device__ float g_bvec[OUT_C];                       // b1 @ W2

// ---------------------------------------------------------------------------
// K1: zero degree counters
// ---------------------------------------------------------------------------
__global__ void k_zero_deg() {
    int i = blockIdx.x * blockDim.x + threadIdx.x;
    if (i < N_NODES) g_deg[i] = 0;
}

// K2: count in-degree, 16 edges/thread (N_EDGES % 16 == 0), no-return atomics
__global__ __launch_bounds__(256) void k_count_deg(const int4* __restrict__ dst4) {
    int i = blockIdx.x * blockDim.x + threadIdx.x;
    if (i >= N_EDGES / 16) return;
#pragma unroll
    for (int q = 0; q < 4; q++) {
        int4 d = __ldg(&dst4[4 * i + q]);
        atomicAdd(&g_deg[d.x], 1);
        atomicAdd(&g_deg[d.y], 1);
        atomicAdd(&g_deg[d.z], 1);
        atomicAdd(&g_deg[d.w], 1);
    }
}

// K3: per-block degree sums
__global__ void k_bsum() {
    __shared__ int wsum[SCAN_BS / 32];
    int t = threadIdx.x;
    int i = blockIdx.x * SCAN_BS + t;
    int v = (i < N_NODES) ? g_deg[i] : 0;
#pragma unroll
    for (int o = 16; o; o >>= 1) v += __shfl_xor_sync(0xffffffffu, v, o);
    if ((t & 31) == 0) wsum[t >> 5] = v;
    __syncthreads();
    if (t < 32) {
        int w = (t < SCAN_BS / 32) ? wsum[t] : 0;
#pragma unroll
        for (int o = 16; o; o >>= 1) w += __shfl_xor_sync(0xffffffffu, w, o);
        if (t == 0) g_bsum[blockIdx.x] = w;
    }
}

// ---------------------------------------------------------------------------
// K4 (fused): blocks 0..SCAN_NB-1 — redundant in-block scan of the 196 block
// sums, local exclusive scan, rowoff/cursor/dinv, and ys0 pack (x staged
// through smem with fully coalesced loads).
// Block SCAN_NB — fused weights Wc/bvec, pad-row zeroing, rowoff[N].
// ---------------------------------------------------------------------------
__global__ __launch_bounds__(SCAN_BS) void k_fuse(const float* __restrict__ x,
                                                  const float* __restrict__ W1,
                                                  const float* __restrict__ b1,
                                                  const float* __restrict__ W2) {
    int t = threadIdx.x;

    if (blockIdx.x == SCAN_NB) {
        // --- weight collapse + housekeeping ---
        if (t < 384) {
            int c = t >> 6;                  // 0..5
            int j = t & 63;
            float s = 0.0f;
            if (c < IN_C) {
                for (int k = 0; k < HID_C; k++)
                    s += W1[c * HID_C + k] * W2[k * OUT_C + j];
                g_Wc[c * OUT_C + j] = s;
            } else {
                for (int k = 0; k < HID_C; k++)
                    s += b1[k] * W2[k * OUT_C + j];
                g_bvec[j] = s;
            }
        } else if (t < 384 + 16) {
            int q = t - 384;                 // 0..15: zero pad rows of ys0/ys1
            if (q < 8)      g_ys0[(size_t)N_NODES * YSTRIDE + q] = 0.f;
            else            g_ys1[(size_t)N_NODES * YSTRIDE + (q - 8)] = 0.f;
        } else if (t == 400) {
            g_rowoff[N_NODES] = N_EDGES;
        }
        return;
    }

    __shared__ int   s196[256];
    __shared__ int   wsum[SCAN_BS / 32];
    __shared__ float sx[SCAN_BS * IN_C];     // 10 KB staging for x

    // --- stage this block's x slab coalesced (5 sweeps) ---
    {
        int base = blockIdx.x * SCAN_BS * IN_C;
        int lim  = N_NODES * IN_C;
#pragma unroll
        for (int q = 0; q < IN_C; q++) {
            int j = q * SCAN_BS + t;
            int gidx = base + j;
            sx[j] = (gidx < lim) ? __ldg(&x[gidx]) : 0.f;
        }
    }

    // --- scan the 196 block sums (redundant per block; cheap) ---
    if (t < 256) s196[t] = (t < SCAN_NB) ? g_bsum[t] : 0;
    __syncthreads();
    for (int o = 1; o < 256; o <<= 1) {
        int u = 0;
        if (t < 256 && t >= o) u = s196[t - o];
        __syncthreads();
        if (t < 256) s196[t] += u;
        __syncthreads();
    }
    int boff = (blockIdx.x == 0) ? 0 : s196[blockIdx.x - 1];

    // --- local exclusive scan over this block's 512 degrees ---
    int lane = t & 31, wid = t >> 5;
    int i = blockIdx.x * SCAN_BS + t;
    int v = (i < N_NODES) ? g_deg[i] : 0;

    int incl = v;
#pragma unroll
    for (int o = 1; o < 32; o <<= 1) {
        int u = __shfl_up_sync(0xffffffffu, incl, o);
        if (lane >= o) incl += u;
    }
    if (lane == 31) wsum[wid] = incl;
    __syncthreads();
    if (wid == 0) {
        int w = (lane < SCAN_BS / 32) ? wsum[lane] : 0;
#pragma unroll
        for (int o = 1; o < SCAN_BS / 32; o <<= 1) {
            int u = __shfl_up_sync(0xffffffffu, w, o);
            if (lane >= o) w += u;
        }
        if (lane < SCAN_BS / 32) wsum[lane] = w;
    }
    __syncthreads();

    if (i < N_NODES) {
        int off = boff + (incl - v) + (wid ? wsum[wid - 1] : 0);
        g_rowoff[i] = off;
        g_cursor[i] = off;
        float dn = rsqrtf((float)(v + 1));   // +1 self-loop
        g_dinv[i] = dn;
        const float* xr = sx + t * IN_C;     // stride 5: bank-conflict-free
        float4* yr = (float4*)(g_ys0 + (size_t)i * YSTRIDE);
        yr[0] = make_float4(dn * xr[0], dn * xr[1], dn * xr[2], dn * xr[3]);
        yr[1] = make_float4(dn * xr[4], dn, 0.f, 0.f);
    }
}

// ---------------------------------------------------------------------------
// K5: bin edges into CSR-by-dst (src only). 16 edges/thread for ATOMG MLP.
// ---------------------------------------------------------------------------
__global__ __launch_bounds__(256) void k_bin(const int4* __restrict__ src4,
                                             const int4* __restrict__ dst4) {
    int i = blockIdx.x * blockDim.x + threadIdx.x;
    if (i >= N_EDGES / 16) return;
#pragma unroll
    for (int q = 0; q < 4; q++) {
        int4 s = __ldg(&src4[4 * i + q]);
        int4 d = __ldg(&dst4[4 * i + q]);
        int p0 = atomicAdd(&g_cursor[d.x], 1);
        int p1 = atomicAdd(&g_cursor[d.y], 1);
        int p2 = atomicAdd(&g_cursor[d.z], 1);
        int p3 = atomicAdd(&g_cursor[d.w], 1);
        g_adj[p0] = s.x;
        g_adj[p1] = s.y;
        g_adj[p2] = s.z;
        g_adj[p3] = s.w;
    }
}

// ---------------------------------------------------------------------------
// Aggregation, warp per node, norm-free inner loop (pure adds).
// PASS 0: ys1[n][c] = dinv²(Σ ys0 + ys0[n]) for c=0..5; ch6 = (Â1)[n].
//         (dinv[n] read from self row's ch5 — no extra dependent load)
// PASS 1: out2_c = dinv(Σ ys1 + ys1[n]) for c=0..4; fused output projection.
// ---------------------------------------------------------------------------
template <int PASS>
__global__ __launch_bounds__(256) void k_agg(float* __restrict__ z,
                                             const float* __restrict__ b2) {
    const float* __restrict__ yin = (PASS == 0) ? g_ys0 : g_ys1;

    int warp = (blockIdx.x * blockDim.x + threadIdx.x) >> 5;
    int lane = threadIdx.x & 31;
    if (warp >= N_NODES) return;
    int n  = warp;
    int ro = __ldg(&g_rowoff[n]);
    int re = __ldg(&g_rowoff[n + 1]);

    float a0 = 0.f, a1 = 0.f, a2 = 0.f, a3 = 0.f, a4 = 0.f, a5 = 0.f;

    for (int base = ro; base < re; base += 32) {
        int k = base + lane;
        int s = (k < re) ? __ldg(&g_adj[k]) : N_NODES;   // pad row = zeros
        const float4* yr = (const float4*)(yin + (size_t)s * YSTRIDE);
        float4 v0 = __ldg(yr);
        float4 v1 = __ldg(yr + 1);
        a0 += v0.x;  a1 += v0.y;  a2 += v0.z;  a3 += v0.w;  a4 += v1.x;
        if (PASS == 0) a5 += v1.y;
    }

#pragma unroll
    for (int o = 16; o; o >>= 1) {
        a0 += __shfl_xor_sync(0xffffffffu, a0, o);
        a1 += __shfl_xor_sync(0xffffffffu, a1, o);
        a2 += __shfl_xor_sync(0xffffffffu, a2, o);
        a3 += __shfl_xor_sync(0xffffffffu, a3, o);
        a4 += __shfl_xor_sync(0xffffffffu, a4, o);
        if (PASS == 0) a5 += __shfl_xor_sync(0xffffffffu, a5, o);
    }

    const float4* yr = (const float4*)(yin + (size_t)n * YSTRIDE);
    float4 s0 = __ldg(yr);                // self row (broadcast)
    float4 s1 = __ldg(yr + 1);

    if (PASS == 0) {
        float dn = s1.y;                  // ys0 ch5 == dinv[n]
        float o0 = dn * (a0 + s0.x);
        float o1 = dn * (a1 + s0.y);
        float o2 = dn * (a2 + s0.z);
        float o3 = dn * (a3 + s0.w);
        float o4 = dn * (a4 + s1.x);
        float o5 = dn * (a5 + s1.y);      // (Â1)[n], unscaled
        if (lane == 0) {
            float4* d4 = (float4*)(g_ys1 + (size_t)n * YSTRIDE);
            d4[0] = make_float4(dn * o0, dn * o1, dn * o2, dn * o3);
            d4[1] = make_float4(dn * o4, dn * o5, o5, 0.f);
        }
    } else {
        float dn = __ldg(&g_dinv[n]);
        float o0 = dn * (a0 + s0.x);
        float o1 = dn * (a1 + s0.y);
        float o2 = dn * (a2 + s0.z);
        float o3 = dn * (a3 + s0.w);
        float o4 = dn * (a4 + s1.x);
        float ab1 = s1.z;                 // (Â1)[n] stashed in channel 6
        float* zr = z + (size_t)n * OUT_C;
#pragma unroll
        for (int h = 0; h < 2; h++) {
            int j = lane + h * 32;
            float acc = __ldg(&b2[j]) + ab1 * g_bvec[j];
            acc += o0 * g_Wc[0 * OUT_C + j];
            acc += o1 * g_Wc[1 * OUT_C + j];
            acc += o2 * g_Wc[2 * OUT_C + j];
            acc += o3 * g_Wc[3 * OUT_C + j];
            acc += o4 * g_Wc[4 * OUT_C + j];
            zr[j] = acc;
        }
    }
}

// ---------------------------------------------------------------------------
// Launch. Inputs (metadata order): x, edge_index, W1, b1, W2, b2.
// ---------------------------------------------------------------------------
extern "C" void kernel_launch(void* const* d_in, const int* in_sizes, int n_in,
                              void* d_out, int out_size) {
    const float* x  = (const float*)d_in[0];
    const int*   ei = (const int*)d_in[1];
    const float* W1 = (const float*)d_in[2];
    const float* b1 = (const float*)d_in[3];
    const float* W2 = (const float*)d_in[4];
    const float* b2 = (const float*)d_in[5];
    float* z = (float*)d_out;

    const int4* src4 = (const int4*)ei;
    const int4* dst4 = (const int4*)(ei + N_EDGES);

    k_zero_deg  <<<(N_NODES + 255) / 256, 256>>>();
    k_count_deg <<<(N_EDGES / 16 + 255) / 256, 256>>>(dst4);
    k_bsum      <<<SCAN_NB, SCAN_BS>>>();
    k_fuse      <<<SCAN_NB + 1, SCAN_BS>>>(x, W1, b1, W2);
    k_bin       <<<(N_EDGES / 16 + 255) / 256, 256>>>(src4, dst4);

    k_agg<0>    <<<(N_NODES + 7) / 8, 256>>>(z, b2);
    k_agg<1>    <<<(N_NODES + 7) / 8, 256>>>(z, b2);
}

// round 10
// speedup vs baseline: 1.4556x; 1.4556x over previous
#include <cuda_runtime.h>
#include <cuda_bf16.h>

#define N_NODES 100000
#define N_EDGES 3200000
#define IN_C 5
#define OUT_C 64
#define HID_C 128
#define YSTRIDE 8              // 6 used channels + spare, 32B row = 1 sector

#define SCAN_BS 512
#define SCAN_NB ((N_NODES + SCAN_BS - 1) / SCAN_BS)   // 196

// ---------------------------------------------------------------------------
// Scratch (device globals; no allocation allowed)
// ---------------------------------------------------------------------------
__device__ int   g_deg[N_NODES];
__device__ int   g_bsum[SCAN_NB];
__device__ int   g_rowoff[N_NODES + 1];
__device__ int   g_cursor[N_NODES];
__device__ float g_dinv[N_NODES];
__device__ int   g_adj[N_EDGES];                      // src only, CSR by dst
__device__ float g_ys0[(N_NODES + 1) * YSTRIDE];      // dinv*[x | 1]; row N = 0
__device__ float g_ys1[(N_NODES + 1) * YSTRIDE];      // dinv*out1 (+ ch6 = Â1)
__device__ float g_Wc[IN_C * OUT_C];                  // W1 @ W2  (5x64)
__device__ float g_bvec[OUT_C];                       // b1 @ W2

// ---------------------------------------------------------------------------
// K1: count in-degree, 8 edges/thread (N_EDGES % 8 == 0), no-return atomics
// ---------------------------------------------------------------------------
__global__ __launch_bounds__(256) void k_count_deg(const int4* __restrict__ dst4) {
    int i = blockIdx.x * blockDim.x + threadIdx.x;
    if (i >= N_EDGES / 8) return;
    int4 d0 = __ldg(&dst4[2 * i]);
    int4 d1 = __ldg(&dst4[2 * i + 1]);
    atomicAdd(&g_deg[d0.x], 1);
    atomicAdd(&g_deg[d0.y], 1);
    atomicAdd(&g_deg[d0.z], 1);
    atomicAdd(&g_deg[d0.w], 1);
    atomicAdd(&g_deg[d1.x], 1);
    atomicAdd(&g_deg[d1.y], 1);
    atomicAdd(&g_deg[d1.z], 1);
    atomicAdd(&g_deg[d1.w], 1);
}

// K2: per-block degree sums
__global__ void k_bsum() {
    __shared__ int wsum[SCAN_BS / 32];
    int t = threadIdx.x;
    int i = blockIdx.x * SCAN_BS + t;
    int v = (i < N_NODES) ? g_deg[i] : 0;
#pragma unroll
    for (int o = 16; o; o >>= 1) v += __shfl_xor_sync(0xffffffffu, v, o);
    if ((t & 31) == 0) wsum[t >> 5] = v;
    __syncthreads();
    if (t < 32) {
        int w = (t < SCAN_BS / 32) ? wsum[t] : 0;
#pragma unroll
        for (int o = 16; o; o >>= 1) w += __shfl_xor_sync(0xffffffffu, w, o);
        if (t == 0) g_bsum[blockIdx.x] = w;
    }
}

// ---------------------------------------------------------------------------
// K3 (fused): blocks 0..SCAN_NB-1 — redundant in-block scan of the 196 block
// sums, local exclusive scan, rowoff/cursor/dinv, and ys0 pack.
// Block SCAN_NB — fused weights Wc/bvec, pad-row zeroing, rowoff[N].
// ---------------------------------------------------------------------------
__global__ void k_fuse(const float* __restrict__ x,
                       const float* __restrict__ W1,
                       const float* __restrict__ b1,
                       const float* __restrict__ W2) {
    int t = threadIdx.x;

    if (blockIdx.x == SCAN_NB) {
        // --- weight collapse + housekeeping ---
        if (t < 384) {
            int c = t >> 6;                  // 0..5
            int j = t & 63;
            float s = 0.0f;
            if (c < IN_C) {
                for (int k = 0; k < HID_C; k++)
                    s += W1[c * HID_C + k] * W2[k * OUT_C + j];
                g_Wc[c * OUT_C + j] = s;
            } else {
                for (int k = 0; k < HID_C; k++)
                    s += b1[k] * W2[k * OUT_C + j];
                g_bvec[j] = s;
            }
        } else if (t < 384 + 16) {
            int q = t - 384;                 // 0..15: zero pad rows of ys0/ys1
            if (q < 8)      g_ys0[(size_t)N_NODES * YSTRIDE + q] = 0.f;
            else            g_ys1[(size_t)N_NODES * YSTRIDE + (q - 8)] = 0.f;
        } else if (t == 400) {
            g_rowoff[N_NODES] = N_EDGES;
        }
        return;
    }

    // --- scan the 196 block sums (redundant per block; cheap) ---
    __shared__ int s196[256];
    __shared__ int wsum[SCAN_BS / 32];
    if (t < 256) s196[t] = (t < SCAN_NB) ? g_bsum[t] : 0;
    __syncthreads();
    for (int o = 1; o < 256; o <<= 1) {
        int u = 0;
        if (t < 256 && t >= o) u = s196[t - o];
        __syncthreads();
        if (t < 256) s196[t] += u;
        __syncthreads();
    }
    int boff = (blockIdx.x == 0) ? 0 : s196[blockIdx.x - 1];

    // --- local exclusive scan over this block's 512 degrees ---
    int lane = t & 31, wid = t >> 5;
    int i = blockIdx.x * SCAN_BS + t;
    int v = (i < N_NODES) ? g_deg[i] : 0;

    int incl = v;
#pragma unroll
    for (int o = 1; o < 32; o <<= 1) {
        int u = __shfl_up_sync(0xffffffffu, incl, o);
        if (lane >= o) incl += u;
    }
    if (lane == 31) wsum[wid] = incl;
    __syncthreads();
    if (wid == 0) {
        int w = (lane < SCAN_BS / 32) ? wsum[lane] : 0;
#pragma unroll
        for (int o = 1; o < SCAN_BS / 32; o <<= 1) {
            int u = __shfl_up_sync(0xffffffffu, w, o);
            if (lane >= o) w += u;
        }
        if (lane < SCAN_BS / 32) wsum[lane] = w;
    }
    __syncthreads();

    if (i < N_NODES) {
        int off = boff + (incl - v) + (wid ? wsum[wid - 1] : 0);
        g_rowoff[i] = off;
        g_cursor[i] = off;
        float dn = rsqrtf((float)(v + 1));   // +1 self-loop
        g_dinv[i] = dn;
        // pack pre-scaled features
        const float* xr = x + (size_t)i * IN_C;
        float4* yr = (float4*)(g_ys0 + (size_t)i * YSTRIDE);
        yr[0] = make_float4(dn * xr[0], dn * xr[1], dn * xr[2], dn * xr[3]);
        yr[1] = make_float4(dn * xr[4], dn, 0.f, 0.f);
    }
}

// ---------------------------------------------------------------------------
// K4: bin edges into CSR-by-dst (src only). 8 edges/thread for ATOMG MLP.
// ---------------------------------------------------------------------------
__global__ __launch_bounds__(256) void k_bin(const int4* __restrict__ src4,
                                             const int4* __restrict__ dst4) {
    int i = blockIdx.x * blockDim.x + threadIdx.x;
    if (i >= N_EDGES / 8) return;
    int4 s0 = __ldg(&src4[2 * i]);
    int4 s1 = __ldg(&src4[2 * i + 1]);
    int4 d0 = __ldg(&dst4[2 * i]);
    int4 d1 = __ldg(&dst4[2 * i + 1]);
    int p0 = atomicAdd(&g_cursor[d0.x], 1);
    int p1 = atomicAdd(&g_cursor[d0.y], 1);
    int p2 = atomicAdd(&g_cursor[d0.z], 1);
    int p3 = atomicAdd(&g_cursor[d0.w], 1);
    int p4 = atomicAdd(&g_cursor[d1.x], 1);
    int p5 = atomicAdd(&g_cursor[d1.y], 1);
    int p6 = atomicAdd(&g_cursor[d1.z], 1);
    int p7 = atomicAdd(&g_cursor[d1.w], 1);
    g_adj[p0] = s0.x;
    g_adj[p1] = s0.y;
    g_adj[p2] = s0.z;
    g_adj[p3] = s0.w;
    g_adj[p4] = s1.x;
    g_adj[p5] = s1.y;
    g_adj[p6] = s1.z;
    g_adj[p7] = s1.w;
}

// ---------------------------------------------------------------------------
// Aggregation, warp per node, norm-free inner loop (pure adds).
// PASS 0: ys1[n][c] = dinv²(Σ ys0 + ys0[n]) for c=0..5; ch6 = (Â1)[n].
//         (dinv[n] read from self row's ch5 — no extra dependent load)
// PASS 1: out2_c = dinv(Σ ys1 + ys1[n]) for c=0..4; fused output projection.
// ---------------------------------------------------------------------------
template <int PASS>
__global__ __launch_bounds__(256) void k_agg(float* __restrict__ z,
                                             const float* __restrict__ b2) {
    const float* __restrict__ yin = (PASS == 0) ? g_ys0 : g_ys1;

    int warp = (blockIdx.x * blockDim.x + threadIdx.x) >> 5;
    int lane = threadIdx.x & 31;
    if (warp >= N_NODES) return;
    int n  = warp;
    int ro = __ldg(&g_rowoff[n]);
    int re = __ldg(&g_rowoff[n + 1]);

    float a0 = 0.f, a1 = 0.f, a2 = 0.f, a3 = 0.f, a4 = 0.f, a5 = 0.f;

    for (int base = ro; base < re; base += 32) {
        int k = base + lane;
        int s = (k < re) ? __ldg(&g_adj[k]) : N_NODES;   // pad row = zeros
        const float4* yr = (const float4*)(yin + (size_t)s * YSTRIDE);
        float4 v0 = __ldg(yr);
        float4 v1 = __ldg(yr + 1);
        a0 += v0.x;  a1 += v0.y;  a2 += v0.z;  a3 += v0.w;  a4 += v1.x;
        if (PASS == 0) a5 += v1.y;
    }

#pragma unroll
    for (int o = 16; o; o >>= 1) {
        a0 += __shfl_xor_sync(0xffffffffu, a0, o);
        a1 += __shfl_xor_sync(0xffffffffu, a1, o);
        a2 += __shfl_xor_sync(0xffffffffu, a2, o);
        a3 += __shfl_xor_sync(0xffffffffu, a3, o);
        a4 += __shfl_xor_sync(0xffffffffu, a4, o);
        if (PASS == 0) a5 += __shfl_xor_sync(0xffffffffu, a5, o);
    }

    const float4* yr = (const float4*)(yin + (size_t)n * YSTRIDE);
    float4 s0 = __ldg(yr);                // self row (broadcast)
    float4 s1 = __ldg(yr + 1);

    if (PASS == 0) {
        float dn = s1.y;                  // ys0 ch5 == dinv[n]
        float o0 = dn * (a0 + s0.x);
        float o1 = dn * (a1 + s0.y);
        float o2 = dn * (a2 + s0.z);
        float o3 = dn * (a3 + s0.w);
        float o4 = dn * (a4 + s1.x);
        float o5 = dn * (a5 + s1.y);      // (Â1)[n], unscaled
        if (lane == 0) {
            float4* d4 = (float4*)(g_ys1 + (size_t)n * YSTRIDE);
            d4[0] = make_float4(dn * o0, dn * o1, dn * o2, dn * o3);
            d4[1] = make_float4(dn * o4, dn * o5, o5, 0.f);
        }
    } else {
        float dn = __ldg(&g_dinv[n]);
        float o0 = dn * (a0 + s0.x);
        float o1 = dn * (a1 + s0.y);
        float o2 = dn * (a2 + s0.z);
        float o3 = dn * (a3 + s0.w);
        float o4 = dn * (a4 + s1.x);
        float ab1 = s1.z;                 // (Â1)[n] stashed in channel 6
        float* zr = z + (size_t)n * OUT_C;
#pragma unroll
        for (int h = 0; h < 2; h++) {
            int j = lane + h * 32;
            float acc = __ldg(&b2[j]) + ab1 * g_bvec[j];
            acc += o0 * g_Wc[0 * OUT_C + j];
            acc += o1 * g_Wc[1 * OUT_C + j];
            acc += o2 * g_Wc[2 * OUT_C + j];
            acc += o3 * g_Wc[3 * OUT_C + j];
            acc += o4 * g_Wc[4 * OUT_C + j];
            zr[j] = acc;
        }
    }
}

// ---------------------------------------------------------------------------
// Launch. Inputs (metadata order): x, edge_index, W1, b1, W2, b2.
// ---------------------------------------------------------------------------
extern "C" void kernel_launch(void* const* d_in, const int* in_sizes, int n_in,
                              void* d_out, int out_size) {
    const float* x  = (const float*)d_in[0];
    const int*   ei = (const int*)d_in[1];
    const float* W1 = (const float*)d_in[2];
    const float* b1 = (const float*)d_in[3];
    const float* W2 = (const float*)d_in[4];
    const float* b2 = (const float*)d_in[5];
    float* z = (float*)d_out;

    const int4* src4 = (const int4*)ei;
    const int4* dst4 = (const int4*)(ei + N_EDGES);

    // zero degree counters via async memset (graph-capturable, no alloc)
    void* deg_ptr = nullptr;
    cudaGetSymbolAddress(&deg_ptr, g_deg);
    cudaMemsetAsync(deg_ptr, 0, N_NODES * sizeof(int));

    k_count_deg <<<(N_EDGES / 8 + 255) / 256, 256>>>(dst4);
    k_bsum      <<<SCAN_NB, SCAN_BS>>>();
    k_fuse      <<<SCAN_NB + 1, SCAN_BS>>>(x, W1, b1, W2);
    k_bin       <<<(N_EDGES / 8 + 255) / 256, 256>>>(src4, dst4);

    k_agg<0>    <<<(N_NODES + 7) / 8, 256>>>(z, b2);
    k_agg<1>    <<<(N_NODES + 7) / 8, 256>>>(z, b2);
}